// round 8
// baseline (speedup 1.0000x reference)
#include <cuda_runtime.h>
#include <cstdint>

#define B_ 8
#define T_ 2048
#define D_ 1024
#define H_ 64
#define M_ (B_ * T_)        // 16384 rows

// ---------------------------------------------------------------------------
// Device scratch
// ---------------------------------------------------------------------------
__device__ float g_V[M_ * H_];                      // fp32 V (intermediate)
__device__ uint32_t g_Qh[M_ * 32], g_Ql[M_ * 32];   // packed bf16 hi/lo Q (pre-scaled)
__device__ uint32_t g_Kh[M_ * 32], g_Kl[M_ * 32];   // packed bf16 hi/lo K
__device__ uint32_t g_Vth[256 * 64 * 32];           // V^T bf16 hi, [tile][dim][keypair]
__device__ uint32_t g_Vtl[256 * 64 * 32];           // V^T bf16 lo

// W transposed, bf16 hi/lo split, packed 2-per-u32 along k
__device__ uint32_t g_Whl[6][64][512];

// Split-KV partials (max 4 splits of 8 tiles)
__device__ float g_Op[B_][32][4][64][H_];
__device__ float g_Ml[B_][32][4][64][2];

// ---------------------------------------------------------------------------
// Helpers
// ---------------------------------------------------------------------------
__device__ __forceinline__ uint32_t smem_u32(const void* p) {
    uint32_t a;
    asm("{ .reg .u64 t; cvta.to.shared.u64 t, %1; cvt.u32.u64 %0, t; }" : "=r"(a) : "l"(p));
    return a;
}
__device__ __forceinline__ uint32_t packbf(float elo, float ehi) {
    uint32_t r;
    asm("cvt.rn.bf16x2.f32 %0, %1, %2;" : "=r"(r) : "f"(ehi), "f"(elo));
    return r;
}
__device__ __forceinline__ float bflo(uint32_t p) { return __uint_as_float(p << 16); }
__device__ __forceinline__ float bfhi(uint32_t p) { return __uint_as_float(p & 0xffff0000u); }

__device__ __forceinline__ void mma_bf16(float* c,
    uint32_t a0, uint32_t a1, uint32_t a2, uint32_t a3, uint32_t b0, uint32_t b1)
{
    asm volatile("mma.sync.aligned.m16n8k16.row.col.f32.bf16.bf16.f32 "
        "{%0,%1,%2,%3}, {%4,%5,%6,%7}, {%8,%9}, {%0,%1,%2,%3};"
        : "+f"(c[0]), "+f"(c[1]), "+f"(c[2]), "+f"(c[3])
        : "r"(a0), "r"(a1), "r"(a2), "r"(a3), "r"(b0), "r"(b1));
}
__device__ __forceinline__ void cp_async16(uint32_t dst, const void* src) {
    asm volatile("cp.async.cg.shared.global [%0], [%1], 16;" :: "r"(dst), "l"(src) : "memory");
}
#define CP_COMMIT()  asm volatile("cp.async.commit_group;" ::: "memory")
#define CP_WAIT1()   asm volatile("cp.async.wait_group 1;"  ::: "memory")
#define CP_WAIT0()   asm volatile("cp.async.wait_group 0;"  ::: "memory")

// ---------------------------------------------------------------------------
// Kernel 0: transpose + bf16 hi/lo split + pack of the three weight matrices.
// ---------------------------------------------------------------------------
__global__ __launch_bounds__(256) void wsplit_kernel(
    const float* __restrict__ Wq, const float* __restrict__ Wk, const float* __restrict__ Wv)
{
    int idx = blockIdx.x * 256 + threadIdx.x;
    int o  = idx >> 15;
    int n  = (idx >> 9) & 63;
    int kp = idx & 511;
    const float* W = (o == 0) ? Wq : (o == 1) ? Wk : Wv;
    float w0 = W[(2 * kp + 0) * 64 + n];
    float w1 = W[(2 * kp + 1) * 64 + n];
    uint32_t hp = packbf(w0, w1);
    uint32_t lp = packbf(w0 - bflo(hp), w1 - bfhi(hp));
    g_Whl[o][n][kp]     = hp;
    g_Whl[3 + o][n][kp] = lp;
}

// ---------------------------------------------------------------------------
// Kernel 1: fused QKV projection via mma.sync bf16 (3-term split).
// M-tile 64 -> 256 CTAs x 128 threads, 2 CTAs/SM: full 148-SM occupancy.
// Stage layout (u32): xs_hi [64][20] @0, xs_lo @1280, ws [6][64][20] @2560.
// ---------------------------------------------------------------------------
#define STAGE_U   10240
#define SMEM_DYN  (2 * STAGE_U * 4)

__global__ __launch_bounds__(128, 2) void qkv_mma_kernel(
    const float* __restrict__ x,
    const float* __restrict__ bq, const float* __restrict__ bk, const float* __restrict__ bv)
{
    extern __shared__ uint32_t sm[];
    __shared__ float sbias[3][64];

    const int tid  = threadIdx.x;
    const int w    = tid >> 5;
    const int lane = tid & 31;
    const int gid  = lane >> 2;
    const int tg   = lane & 3;
    const int m0   = blockIdx.x * 64;

    if (tid < 64) {
        sbias[0][tid] = bq[tid];
        sbias[1][tid] = bk[tid];
        sbias[2][tid] = bv[tid];
    }

    const int xrow  = tid >> 1;      // 0..63
    const int xhalf = tid & 1;
    const float* xbase = x + (size_t)(m0 + xrow) * D_ + xhalf * 16;

    uint32_t wdst[12];
    const uint32_t* wsrc[12];
    #pragma unroll
    for (int it = 0; it < 12; it++) {
        int sid = it * 128 + tid;            // 0..1535
        int j = sid >> 8, n = (sid >> 2) & 63, gq = sid & 3;
        wdst[it] = 2560u + (uint32_t)j * 1280u + (uint32_t)n * 20u + (uint32_t)gq * 4u;
        wsrc[it] = &g_Whl[j][n][gq * 4];
    }
    const uint32_t smbase = smem_u32(sm);

    float acc[3][8][4];
    #pragma unroll
    for (int o = 0; o < 3; o++)
        #pragma unroll
        for (int nt = 0; nt < 8; nt++)
            #pragma unroll
            for (int i = 0; i < 4; i++) acc[o][nt][i] = 0.0f;

    #pragma unroll
    for (int it = 0; it < 12; it++)
        cp_async16(smbase + wdst[it] * 4, wsrc[it]);
    CP_COMMIT();

    float4 xv[2][4];
    #pragma unroll
    for (int i = 0; i < 4; i++) xv[0][i] = *(const float4*)(xbase + i * 4);

    #pragma unroll 2
    for (int s = 0; s < 32; s++) {
        const int p   = s & 1;
        const int np  = p ^ 1;
        const uint32_t st = (uint32_t)p * STAGE_U;

        if (s + 1 < 32) {
            #pragma unroll
            for (int it = 0; it < 12; it++)
                cp_async16(smbase + (np * STAGE_U + wdst[it]) * 4,
                           wsrc[it] + (size_t)(s + 1) * 16);
        }
        CP_COMMIT();
        if (s + 1 < 32) {
            const float* xp = xbase + (s + 1) * 32;
            #pragma unroll
            for (int i = 0; i < 4; i++) xv[np][i] = *(const float4*)(xp + i * 4);
        }

        {
            uint32_t hp[8], lp[8];
            #pragma unroll
            for (int i = 0; i < 4; i++) {
                float4 v = xv[p][i];
                uint32_t h01 = packbf(v.x, v.y);
                uint32_t h23 = packbf(v.z, v.w);
                hp[i * 2 + 0] = h01; hp[i * 2 + 1] = h23;
                lp[i * 2 + 0] = packbf(v.x - bflo(h01), v.y - bfhi(h01));
                lp[i * 2 + 1] = packbf(v.z - bflo(h23), v.w - bfhi(h23));
            }
            uint32_t* xhi = &sm[st + (uint32_t)xrow * 20u + (uint32_t)xhalf * 8u];
            uint32_t* xlo = xhi + 1280;
            *(uint4*)(xhi + 0) = make_uint4(hp[0], hp[1], hp[2], hp[3]);
            *(uint4*)(xhi + 4) = make_uint4(hp[4], hp[5], hp[6], hp[7]);
            *(uint4*)(xlo + 0) = make_uint4(lp[0], lp[1], lp[2], lp[3]);
            *(uint4*)(xlo + 4) = make_uint4(lp[4], lp[5], lp[6], lp[7]);
        }

        CP_WAIT1();
        __syncthreads();

        const uint32_t arow = st + (uint32_t)(w * 16 + gid) * 20u;
        #pragma unroll
        for (int kk = 0; kk < 2; kk++) {
            const uint32_t ka = arow + kk * 8 + tg;
            uint32_t ah0 = sm[ka];
            uint32_t ah1 = sm[ka + 8 * 20];
            uint32_t ah2 = sm[ka + 4];
            uint32_t ah3 = sm[ka + 8 * 20 + 4];
            uint32_t al0 = sm[ka + 1280];
            uint32_t al1 = sm[ka + 1280 + 8 * 20];
            uint32_t al2 = sm[ka + 1280 + 4];
            uint32_t al3 = sm[ka + 1280 + 8 * 20 + 4];
            #pragma unroll
            for (int o = 0; o < 3; o++) {
                #pragma unroll
                for (int nt = 0; nt < 8; nt++) {
                    const uint32_t kb = st + 2560u + (uint32_t)o * 1280u
                                      + (uint32_t)(nt * 8 + gid) * 20u + kk * 8 + tg;
                    uint32_t bh0 = sm[kb];
                    uint32_t bh1 = sm[kb + 4];
                    uint32_t bl0 = sm[kb + 3 * 1280];
                    uint32_t bl1 = sm[kb + 3 * 1280 + 4];
                    mma_bf16(acc[o][nt], ah0, ah1, ah2, ah3, bh0, bh1);
                    mma_bf16(acc[o][nt], ah0, ah1, ah2, ah3, bl0, bl1);
                    mma_bf16(acc[o][nt], al0, al1, al2, al3, bh0, bh1);
                }
            }
        }
        __syncthreads();
    }

    // epilogue: Q,K -> packed bf16 hi/lo; V -> fp32
    const int r0 = m0 + w * 16 + gid;
    #pragma unroll
    for (int o = 0; o < 3; o++) {
        const float scale = (o == 0) ? 0.125f : 1.0f;
        #pragma unroll
        for (int nt = 0; nt < 8; nt++) {
            const int col = nt * 8 + 2 * tg;
            float v00 = (acc[o][nt][0] + sbias[o][col])     * scale;
            float v01 = (acc[o][nt][1] + sbias[o][col + 1]) * scale;
            float v10 = (acc[o][nt][2] + sbias[o][col])     * scale;
            float v11 = (acc[o][nt][3] + sbias[o][col + 1]) * scale;
            if (o == 2) {
                *(float2*)(g_V + (size_t)r0 * H_ + col)       = make_float2(v00, v01);
                *(float2*)(g_V + (size_t)(r0 + 8) * H_ + col) = make_float2(v10, v11);
            } else {
                uint32_t* gh = (o == 0) ? g_Qh : g_Kh;
                uint32_t* gl = (o == 0) ? g_Ql : g_Kl;
                const int pi = nt * 4 + tg;
                uint32_t h0 = packbf(v00, v01);
                uint32_t h1 = packbf(v10, v11);
                gh[(size_t)r0 * 32 + pi]       = h0;
                gh[(size_t)(r0 + 8) * 32 + pi] = h1;
                gl[(size_t)r0 * 32 + pi]       = packbf(v00 - bflo(h0), v01 - bfhi(h0));
                gl[(size_t)(r0 + 8) * 32 + pi] = packbf(v10 - bflo(h1), v11 - bfhi(h1));
            }
        }
    }
}

// ---------------------------------------------------------------------------
// Kernel 1b: V -> transposed bf16 hi/lo split [tile][dim][keypair].
// One CTA per 64-key tile; smem transpose for coalescing both sides.
// ---------------------------------------------------------------------------
__global__ __launch_bounds__(256) void vsplit_kernel()
{
    __shared__ float vs[64][65];
    const int bt  = blockIdx.x;            // 0..255
    const int tid = threadIdx.x;
    const float* base = g_V + (size_t)bt * 64 * 64;

    #pragma unroll
    for (int i = 0; i < 16; i++) {
        int id = i * 256 + tid;
        vs[id >> 6][id & 63] = base[id];
    }
    __syncthreads();

    const int d   = tid >> 2;
    const int kpb = (tid & 3) * 8;
    uint32_t* oh = g_Vth + (size_t)bt * 2048 + d * 32;
    uint32_t* ol = g_Vtl + (size_t)bt * 2048 + d * 32;
    #pragma unroll
    for (int j = 0; j < 8; j++) {
        int kp = kpb + j;
        float v0 = vs[2 * kp][d];
        float v1 = vs[2 * kp + 1][d];
        uint32_t hp = packbf(v0, v1);
        oh[kp] = hp;
        ol[kp] = packbf(v0 - bflo(hp), v1 - bfhi(hp));
    }
}

// ---------------------------------------------------------------------------
// Kernel 2: split-KV causal flash attention, mma.sync bf16, 3-term split.
// Split size 8 tiles -> grid (80, 8) LPT-decoded.  block 128 = 4 warps.
// All 4 operand tiles (Kh,Kl,Vth,Vtl) cp.async'd through a 2-stage ring
// (stride 36 -> conflict-free fragment LDS).  Single-split q-blocks (t<8)
// normalize and write the output directly; others write (o,m,l) partials.
// Dynamic smem: 4 arrays x 2 stages x 2304 u32 = 73728 B.
// ---------------------------------------------------------------------------
#define AKH 0
#define AKL 4608
#define AVH 9216
#define AVL 13824
#define ATT_SMEM (18432 * 4)

__global__ __launch_bounds__(128) void attn_split_kernel(float* __restrict__ out)
{
    extern __shared__ uint32_t sa[];

    const int bxr = 79 - (int)blockIdx.x;   // heavy first (LPT)
    const int b   = blockIdx.y;

    int g = 0;
    if (bxr >= 8)  g = 1;
    if (bxr >= 24) g = 2;
    if (bxr >= 48) g = 3;
    const int rem = bxr - 4 * g * (g + 1);
    const int qi  = rem / (g + 1);
    const int s   = rem - qi * (g + 1);
    const int t   = 8 * g + qi;              // q-block 0..31

    const int tid  = threadIdx.x;
    const int w    = tid >> 5;
    const int lane = tid & 31;
    const int gid  = lane >> 2;
    const int tg   = lane & 3;
    const int r0   = t * 64 + w * 16 + gid;  // q row (in-batch); second row r0+8

    // Q A-fragments (hi/lo)
    uint32_t qh[4][4], ql[4][4];
    {
        const uint32_t* qhp = g_Qh + ((size_t)b * T_ + r0) * 32;
        const uint32_t* qlp = g_Ql + ((size_t)b * T_ + r0) * 32;
        #pragma unroll
        for (int kk = 0; kk < 4; kk++) {
            qh[kk][0] = qhp[kk * 8 + tg];
            qh[kk][1] = qhp[8 * 32 + kk * 8 + tg];
            qh[kk][2] = qhp[kk * 8 + tg + 4];
            qh[kk][3] = qhp[8 * 32 + kk * 8 + tg + 4];
            ql[kk][0] = qlp[kk * 8 + tg];
            ql[kk][1] = qlp[8 * 32 + kk * 8 + tg];
            ql[kk][2] = qlp[kk * 8 + tg + 4];
            ql[kk][3] = qlp[8 * 32 + kk * 8 + tg + 4];
        }
    }

    float o[8][4];
    #pragma unroll
    for (int nt = 0; nt < 8; nt++)
        #pragma unroll
        for (int i = 0; i < 4; i++) o[nt][i] = 0.0f;
    float m0v = -1e30f, m1v = -1e30f, l0 = 0.0f, l1 = 0.0f;

    const uint32_t sab = smem_u32(sa);
    // per-thread tile-load addressing: 4 chunks per array
    int lrow[4], lgq[4];
    #pragma unroll
    for (int i = 0; i < 4; i++) {
        int c = i * 128 + tid;
        lrow[i] = c >> 3;
        lgq[i]  = c & 7;
    }

    const int t0 = s * 8;
    const int t1 = min(s * 8 + 8, t + 1);
    const int ntile = t1 - t0;

    // prologue load: tile t0 -> stage 0
    {
        const size_t krow = (size_t)b * T_ + t0 * 64;
        const size_t vbs  = ((size_t)b * 32 + t0) * 2048;
        #pragma unroll
        for (int i = 0; i < 4; i++) {
            uint32_t doff = (uint32_t)(lrow[i] * 36 + lgq[i] * 4) * 4;
            uint32_t soff = (krow + lrow[i]) * 32 + lgq[i] * 4;
            cp_async16(sab + AKH * 4 + doff, g_Kh + soff);
            cp_async16(sab + AKL * 4 + doff, g_Kl + soff);
            cp_async16(sab + AVH * 4 + doff, g_Vth + vbs + lrow[i] * 32 + lgq[i] * 4);
            cp_async16(sab + AVL * 4 + doff, g_Vtl + vbs + lrow[i] * 32 + lgq[i] * 4);
        }
        CP_COMMIT();
    }

    for (int ti = 0; ti < ntile; ti++) {
        const int tt = t0 + ti;
        const int p  = ti & 1;
        const uint32_t stp = (uint32_t)p * 2304u;

        if (ti + 1 < ntile) {
            const uint32_t stn = (uint32_t)(p ^ 1) * 2304u;
            const size_t krow = (size_t)b * T_ + (tt + 1) * 64;
            const size_t vbs  = ((size_t)b * 32 + (tt + 1)) * 2048;
            #pragma unroll
            for (int i = 0; i < 4; i++) {
                uint32_t doff = (stn + (uint32_t)(lrow[i] * 36 + lgq[i] * 4)) * 4;
                uint32_t soff = (krow + lrow[i]) * 32 + lgq[i] * 4;
                cp_async16(sab + AKH * 4 + doff, g_Kh + soff);
                cp_async16(sab + AKL * 4 + doff, g_Kl + soff);
                cp_async16(sab + AVH * 4 + doff, g_Vth + vbs + lrow[i] * 32 + lgq[i] * 4);
                cp_async16(sab + AVL * 4 + doff, g_Vtl + vbs + lrow[i] * 32 + lgq[i] * 4);
            }
            CP_COMMIT();
            CP_WAIT1();
        } else {
            CP_WAIT0();
        }
        __syncthreads();

        // ---- S = Q K^T (3-term) ----
        float st[8][4];
        #pragma unroll
        for (int nt = 0; nt < 8; nt++)
            #pragma unroll
            for (int i = 0; i < 4; i++) st[nt][i] = 0.0f;

        #pragma unroll
        for (int kk = 0; kk < 4; kk++) {
            #pragma unroll
            for (int nt = 0; nt < 8; nt++) {
                const uint32_t base = stp + (uint32_t)(nt * 8 + gid) * 36u + kk * 8 + tg;
                uint32_t bh0 = sa[AKH + base], bh1 = sa[AKH + base + 4];
                uint32_t bl0 = sa[AKL + base], bl1 = sa[AKL + base + 4];
                mma_bf16(st[nt], qh[kk][0], qh[kk][1], qh[kk][2], qh[kk][3], bh0, bh1);
                mma_bf16(st[nt], qh[kk][0], qh[kk][1], qh[kk][2], qh[kk][3], bl0, bl1);
                mma_bf16(st[nt], ql[kk][0], ql[kk][1], ql[kk][2], ql[kk][3], bh0, bh1);
            }
        }

        // causal mask (diagonal tile only)
        if (tt == t) {
            #pragma unroll
            for (int nt = 0; nt < 8; nt++) {
                int c0 = tt * 64 + nt * 8 + 2 * tg;
                if (c0     > r0)     st[nt][0] = -1e30f;
                if (c0 + 1 > r0)     st[nt][1] = -1e30f;
                if (c0     > r0 + 8) st[nt][2] = -1e30f;
                if (c0 + 1 > r0 + 8) st[nt][3] = -1e30f;
            }
        }

        // ---- online softmax on fragments ----
        float mn0 = m0v, mn1 = m1v;
        #pragma unroll
        for (int nt = 0; nt < 8; nt++) {
            mn0 = fmaxf(mn0, fmaxf(st[nt][0], st[nt][1]));
            mn1 = fmaxf(mn1, fmaxf(st[nt][2], st[nt][3]));
        }
        mn0 = fmaxf(mn0, __shfl_xor_sync(0xffffffffu, mn0, 1));
        mn0 = fmaxf(mn0, __shfl_xor_sync(0xffffffffu, mn0, 2));
        mn1 = fmaxf(mn1, __shfl_xor_sync(0xffffffffu, mn1, 1));
        mn1 = fmaxf(mn1, __shfl_xor_sync(0xffffffffu, mn1, 2));
        const float a0 = __expf(m0v - mn0);
        const float a1 = __expf(m1v - mn1);
        m0v = mn0; m1v = mn1;
        float rs0 = 0.0f, rs1 = 0.0f;
        #pragma unroll
        for (int nt = 0; nt < 8; nt++) {
            st[nt][0] = __expf(st[nt][0] - mn0);
            st[nt][1] = __expf(st[nt][1] - mn0);
            st[nt][2] = __expf(st[nt][2] - mn1);
            st[nt][3] = __expf(st[nt][3] - mn1);
            rs0 += st[nt][0] + st[nt][1];
            rs1 += st[nt][2] + st[nt][3];
        }
        l0 = l0 * a0 + rs0;
        l1 = l1 * a1 + rs1;
        #pragma unroll
        for (int nt = 0; nt < 8; nt++) {
            o[nt][0] *= a0; o[nt][1] *= a0;
            o[nt][2] *= a1; o[nt][3] *= a1;
        }

        // ---- O += P V (3-term) ----
        #pragma unroll
        for (int kk = 0; kk < 4; kk++) {
            uint32_t ph[4], pl[4];
            ph[0] = packbf(st[2 * kk][0],     st[2 * kk][1]);
            ph[1] = packbf(st[2 * kk][2],     st[2 * kk][3]);
            ph[2] = packbf(st[2 * kk + 1][0], st[2 * kk + 1][1]);
            ph[3] = packbf(st[2 * kk + 1][2], st[2 * kk + 1][3]);
            pl[0] = packbf(st[2 * kk][0]     - bflo(ph[0]), st[2 * kk][1]     - bfhi(ph[0]));
            pl[1] = packbf(st[2 * kk][2]     - bflo(ph[1]), st[2 * kk][3]     - bfhi(ph[1]));
            pl[2] = packbf(st[2 * kk + 1][0] - bflo(ph[2]), st[2 * kk + 1][1] - bfhi(ph[2]));
            pl[3] = packbf(st[2 * kk + 1][2] - bflo(ph[3]), st[2 * kk + 1][3] - bfhi(ph[3]));
            #pragma unroll
            for (int nd = 0; nd < 8; nd++) {
                const uint32_t base = stp + (uint32_t)(nd * 8 + gid) * 36u + kk * 8 + tg;
                uint32_t vh0 = sa[AVH + base], vh1 = sa[AVH + base + 4];
                uint32_t vl0 = sa[AVL + base], vl1 = sa[AVL + base + 4];
                mma_bf16(o[nd], ph[0], ph[1], ph[2], ph[3], vh0, vh1);
                mma_bf16(o[nd], pl[0], pl[1], pl[2], pl[3], vh0, vh1);
                mma_bf16(o[nd], ph[0], ph[1], ph[2], ph[3], vl0, vl1);
            }
        }
        __syncthreads();
    }

    // full-row l (quartet reduce)
    l0 += __shfl_xor_sync(0xffffffffu, l0, 1);
    l0 += __shfl_xor_sync(0xffffffffu, l0, 2);
    l1 += __shfl_xor_sync(0xffffffffu, l1, 1);
    l1 += __shfl_xor_sync(0xffffffffu, l1, 2);

    const int rr = w * 16 + gid;
    if (g == 0) {
        // single split covers everything: normalize and write output directly
        const float i0 = 1.0f / l0, i1 = 1.0f / l1;
        float* o0 = out + ((size_t)b * T_ + t * 64 + rr) * H_;
        float* o1 = out + ((size_t)b * T_ + t * 64 + rr + 8) * H_;
        #pragma unroll
        for (int nt = 0; nt < 8; nt++) {
            const int col = nt * 8 + 2 * tg;
            *(float2*)(o0 + col) = make_float2(o[nt][0] * i0, o[nt][1] * i0);
            *(float2*)(o1 + col) = make_float2(o[nt][2] * i1, o[nt][3] * i1);
        }
    } else {
        float* op0 = &g_Op[b][t][s][rr][0];
        float* op1 = &g_Op[b][t][s][rr + 8][0];
        #pragma unroll
        for (int nt = 0; nt < 8; nt++) {
            const int col = nt * 8 + 2 * tg;
            *(float2*)(op0 + col) = make_float2(o[nt][0], o[nt][1]);
            *(float2*)(op1 + col) = make_float2(o[nt][2], o[nt][3]);
        }
        if (tg == 0) {
            g_Ml[b][t][s][rr][0]     = m0v;
            g_Ml[b][t][s][rr][1]     = l0;
            g_Ml[b][t][s][rr + 8][0] = m1v;
            g_Ml[b][t][s][rr + 8][1] = l1;
        }
    }
}

// ---------------------------------------------------------------------------
// Kernel 3: combine split partials (only q-blocks t >= 8).
// ---------------------------------------------------------------------------
__global__ __launch_bounds__(256) void attn_combine_kernel(float* __restrict__ out)
{
    const int t   = 8 + blockIdx.x;          // 8..31
    const int b   = blockIdx.y;
    const int tid = threadIdx.x;
    const int r   = tid >> 2;
    const int q4  = tid & 3;
    const int dbase = q4 * 16;
    const int ns  = t / 8 + 1;               // 2..4

    float mv[4], lv[4], wv[4];
    float M = -1e30f;
    for (int i = 0; i < ns; i++) {
        mv[i] = g_Ml[b][t][i][r][0];
        lv[i] = g_Ml[b][t][i][r][1];
        M = fmaxf(M, mv[i]);
    }
    float L = 0.0f;
    for (int i = 0; i < ns; i++) {
        wv[i] = __expf(mv[i] - M);
        L += wv[i] * lv[i];
    }
    const float invL = 1.0f / L;

    float acc[16];
    #pragma unroll
    for (int d = 0; d < 16; d++) acc[d] = 0.0f;

    for (int i = 0; i < ns; i++) {
        const float* op = &g_Op[b][t][i][r][dbase];
        const float wi = wv[i];
        #pragma unroll
        for (int d4 = 0; d4 < 4; d4++) {
            float4 v = *(const float4*)(op + d4 * 4);
            acc[d4 * 4 + 0] += wi * v.x;
            acc[d4 * 4 + 1] += wi * v.y;
            acc[d4 * 4 + 2] += wi * v.z;
            acc[d4 * 4 + 3] += wi * v.w;
        }
    }

    float* orow = out + ((size_t)b * T_ + t * 64 + r) * H_ + dbase;
    #pragma unroll
    for (int d4 = 0; d4 < 4; d4++) {
        float4 v;
        v.x = acc[d4 * 4 + 0] * invL;
        v.y = acc[d4 * 4 + 1] * invL;
        v.z = acc[d4 * 4 + 2] * invL;
        v.w = acc[d4 * 4 + 3] * invL;
        *(float4*)(orow + d4 * 4) = v;
    }
}

// ---------------------------------------------------------------------------
extern "C" void kernel_launch(void* const* d_in, const int* in_sizes, int n_in,
                              void* d_out, int out_size)
{
    const float* x  = (const float*)d_in[0];
    const float* Wq = (const float*)d_in[1];
    const float* bq = (const float*)d_in[2];
    const float* Wk = (const float*)d_in[3];
    const float* bk = (const float*)d_in[4];
    const float* Wv = (const float*)d_in[5];
    const float* bv = (const float*)d_in[6];
    float* out = (float*)d_out;

    cudaFuncSetAttribute(qkv_mma_kernel,
                         cudaFuncAttributeMaxDynamicSharedMemorySize, SMEM_DYN);
    cudaFuncSetAttribute(attn_split_kernel,
                         cudaFuncAttributeMaxDynamicSharedMemorySize, ATT_SMEM);

    wsplit_kernel<<<384, 256>>>(Wq, Wk, Wv);
    qkv_mma_kernel<<<256, 128, SMEM_DYN>>>(x, bq, bk, bv);
    vsplit_kernel<<<256, 256>>>();
    attn_split_kernel<<<dim3(80, B_), 128, ATT_SMEM>>>(out);
    attn_combine_kernel<<<dim3(24, B_), 256>>>(out);
}

// round 9
// speedup vs baseline: 1.2119x; 1.2119x over previous
#include <cuda_runtime.h>
#include <cuda_fp16.h>
#include <cstdint>

#define B_ 8
#define T_ 2048
#define D_ 1024
#define H_ 64
#define M_ (B_ * T_)        // 16384 rows

// ---------------------------------------------------------------------------
// Device scratch
// ---------------------------------------------------------------------------
__device__ float g_V[M_ * H_];                      // fp32 V (intermediate)
__device__ uint32_t g_Qh[M_ * 32];                  // packed fp16 Q (pre-scaled), single
__device__ uint32_t g_Kh[M_ * 32], g_Kl[M_ * 32];   // packed fp16 hi/lo K
__device__ uint32_t g_Vth[256 * 64 * 32];           // V^T fp16 hi, [tile][dim][keypair]
__device__ uint32_t g_Vtl[256 * 64 * 32];           // V^T fp16 lo

// W transposed, fp16 hi/lo split, packed 2-per-u32 along k
__device__ uint32_t g_Whl[6][64][512];

// Split-KV partials (max 4 splits of 8 tiles)
__device__ float g_Op[B_][32][4][64][H_];
__device__ float g_Ml[B_][32][4][64][2];

// ---------------------------------------------------------------------------
// Helpers
// ---------------------------------------------------------------------------
__device__ __forceinline__ uint32_t smem_u32(const void* p) {
    uint32_t a;
    asm("{ .reg .u64 t; cvta.to.shared.u64 t, %1; cvt.u32.u64 %0, t; }" : "=r"(a) : "l"(p));
    return a;
}
__device__ __forceinline__ uint32_t packhf(float a, float b) {   // a->lo, b->hi
    __half2 h = __floats2half2_rn(a, b);
    return *reinterpret_cast<uint32_t*>(&h);
}
__device__ __forceinline__ float2 unpackhf(uint32_t p) {
    __half2 h = *reinterpret_cast<__half2*>(&p);
    return __half22float2(h);
}
__device__ __forceinline__ void mma_f16(float* c,
    uint32_t a0, uint32_t a1, uint32_t a2, uint32_t a3, uint32_t b0, uint32_t b1)
{
    asm volatile("mma.sync.aligned.m16n8k16.row.col.f32.f16.f16.f32 "
        "{%0,%1,%2,%3}, {%4,%5,%6,%7}, {%8,%9}, {%0,%1,%2,%3};"
        : "+f"(c[0]), "+f"(c[1]), "+f"(c[2]), "+f"(c[3])
        : "r"(a0), "r"(a1), "r"(a2), "r"(a3), "r"(b0), "r"(b1));
}
__device__ __forceinline__ void cp_async16(uint32_t dst, const void* src) {
    asm volatile("cp.async.cg.shared.global [%0], [%1], 16;" :: "r"(dst), "l"(src) : "memory");
}
#define CP_COMMIT()  asm volatile("cp.async.commit_group;" ::: "memory")
#define CP_WAIT1()   asm volatile("cp.async.wait_group 1;"  ::: "memory")
#define CP_WAIT0()   asm volatile("cp.async.wait_group 0;"  ::: "memory")

// ---------------------------------------------------------------------------
// Kernel 0: transpose + fp16 hi/lo split + pack of the three weight matrices.
// ---------------------------------------------------------------------------
__global__ __launch_bounds__(256) void wsplit_kernel(
    const float* __restrict__ Wq, const float* __restrict__ Wk, const float* __restrict__ Wv)
{
    int idx = blockIdx.x * 256 + threadIdx.x;
    int o  = idx >> 15;
    int n  = (idx >> 9) & 63;
    int kp = idx & 511;
    const float* W = (o == 0) ? Wq : (o == 1) ? Wk : Wv;
    float w0 = W[(2 * kp + 0) * 64 + n];
    float w1 = W[(2 * kp + 1) * 64 + n];
    uint32_t hp = packhf(w0, w1);
    float2 f = unpackhf(hp);
    g_Whl[o][n][kp]     = hp;
    g_Whl[3 + o][n][kp] = packhf(w0 - f.x, w1 - f.y);
}

// ---------------------------------------------------------------------------
// Kernel 1: fused QKV projection, mma.sync fp16, asymmetric 2-mma split:
//   out = x_f16 * (W_hi + W_lo).
// M-tile 128, 128 CTAs x 256 threads.  Stage (u32): xs [128][20] @0 (2560),
// ws [6][64][20] @2560 (7680) -> 10240 u32 = 40 KB, x2 stages.
// Q written pre-scaled by 0.125 as single fp16; K as fp16 hi/lo; V fp32.
// ---------------------------------------------------------------------------
#define STAGE_U   10240
#define SMEM_DYN  (2 * STAGE_U * 4)

__global__ __launch_bounds__(256, 1) void qkv_mma_kernel(
    const float* __restrict__ x,
    const float* __restrict__ bq, const float* __restrict__ bk, const float* __restrict__ bv)
{
    extern __shared__ uint32_t sm[];
    __shared__ float sbias[3][64];

    const int tid  = threadIdx.x;
    const int w    = tid >> 5;
    const int lane = tid & 31;
    const int gid  = lane >> 2;
    const int tg   = lane & 3;
    const int m0   = blockIdx.x * 128;

    if (tid < 64) {
        sbias[0][tid] = bq[tid];
        sbias[1][tid] = bk[tid];
        sbias[2][tid] = bv[tid];
    }

    const int xrow  = tid >> 1;      // 0..127
    const int xhalf = tid & 1;
    const float* xbase = x + (size_t)(m0 + xrow) * D_ + xhalf * 16;

    uint32_t wdst[6];
    const uint32_t* wsrc[6];
    #pragma unroll
    for (int it = 0; it < 6; it++) {
        int sid = it * 256 + tid;            // 0..1535
        int j = sid >> 8, n = (sid >> 2) & 63, gq = sid & 3;
        wdst[it] = 2560u + (uint32_t)j * 1280u + (uint32_t)n * 20u + (uint32_t)gq * 4u;
        wsrc[it] = &g_Whl[j][n][gq * 4];
    }
    const uint32_t smbase = smem_u32(sm);

    float acc[3][8][4];
    #pragma unroll
    for (int o = 0; o < 3; o++)
        #pragma unroll
        for (int nt = 0; nt < 8; nt++)
            #pragma unroll
            for (int i = 0; i < 4; i++) acc[o][nt][i] = 0.0f;

    #pragma unroll
    for (int it = 0; it < 6; it++)
        cp_async16(smbase + wdst[it] * 4, wsrc[it]);
    CP_COMMIT();

    float4 xv[2][4];
    #pragma unroll
    for (int i = 0; i < 4; i++) xv[0][i] = *(const float4*)(xbase + i * 4);

    #pragma unroll 2
    for (int s = 0; s < 32; s++) {
        const int p   = s & 1;
        const int np  = p ^ 1;
        const uint32_t st = (uint32_t)p * STAGE_U;

        if (s + 1 < 32) {
            #pragma unroll
            for (int it = 0; it < 6; it++)
                cp_async16(smbase + (np * STAGE_U + wdst[it]) * 4,
                           wsrc[it] + (size_t)(s + 1) * 16);
        }
        CP_COMMIT();
        if (s + 1 < 32) {
            const float* xp = xbase + (s + 1) * 32;
            #pragma unroll
            for (int i = 0; i < 4; i++) xv[np][i] = *(const float4*)(xp + i * 4);
        }

        // pack + STS x chunk (single fp16): 16 floats -> 8 u32
        {
            uint32_t hp[8];
            #pragma unroll
            for (int i = 0; i < 4; i++) {
                float4 v = xv[p][i];
                hp[i * 2 + 0] = packhf(v.x, v.y);
                hp[i * 2 + 1] = packhf(v.z, v.w);
            }
            uint32_t* xs = &sm[st + (uint32_t)xrow * 20u + (uint32_t)xhalf * 8u];
            *(uint4*)(xs + 0) = make_uint4(hp[0], hp[1], hp[2], hp[3]);
            *(uint4*)(xs + 4) = make_uint4(hp[4], hp[5], hp[6], hp[7]);
        }

        CP_WAIT1();
        __syncthreads();

        const uint32_t arow = st + (uint32_t)(w * 16 + gid) * 20u;
        #pragma unroll
        for (int kk = 0; kk < 2; kk++) {
            const uint32_t ka = arow + kk * 8 + tg;
            uint32_t a0 = sm[ka];
            uint32_t a1 = sm[ka + 8 * 20];
            uint32_t a2 = sm[ka + 4];
            uint32_t a3 = sm[ka + 8 * 20 + 4];
            #pragma unroll
            for (int o = 0; o < 3; o++) {
                #pragma unroll
                for (int nt = 0; nt < 8; nt++) {
                    const uint32_t kb = st + 2560u + (uint32_t)o * 1280u
                                      + (uint32_t)(nt * 8 + gid) * 20u + kk * 8 + tg;
                    uint32_t bh0 = sm[kb];
                    uint32_t bh1 = sm[kb + 4];
                    uint32_t bl0 = sm[kb + 3 * 1280];
                    uint32_t bl1 = sm[kb + 3 * 1280 + 4];
                    mma_f16(acc[o][nt], a0, a1, a2, a3, bh0, bh1);
                    mma_f16(acc[o][nt], a0, a1, a2, a3, bl0, bl1);
                }
            }
        }
        __syncthreads();
    }

    // epilogue: Q -> single fp16; K -> fp16 hi/lo; V -> fp32
    const int r0 = m0 + w * 16 + gid;
    #pragma unroll
    for (int o = 0; o < 3; o++) {
        const float scale = (o == 0) ? 0.125f : 1.0f;
        #pragma unroll
        for (int nt = 0; nt < 8; nt++) {
            const int col = nt * 8 + 2 * tg;
            float v00 = (acc[o][nt][0] + sbias[o][col])     * scale;
            float v01 = (acc[o][nt][1] + sbias[o][col + 1]) * scale;
            float v10 = (acc[o][nt][2] + sbias[o][col])     * scale;
            float v11 = (acc[o][nt][3] + sbias[o][col + 1]) * scale;
            const int pi = nt * 4 + tg;
            if (o == 2) {
                *(float2*)(g_V + (size_t)r0 * H_ + col)       = make_float2(v00, v01);
                *(float2*)(g_V + (size_t)(r0 + 8) * H_ + col) = make_float2(v10, v11);
            } else if (o == 0) {
                g_Qh[(size_t)r0 * 32 + pi]       = packhf(v00, v01);
                g_Qh[(size_t)(r0 + 8) * 32 + pi] = packhf(v10, v11);
            } else {
                uint32_t h0 = packhf(v00, v01);
                uint32_t h1 = packhf(v10, v11);
                float2 f0 = unpackhf(h0), f1 = unpackhf(h1);
                g_Kh[(size_t)r0 * 32 + pi]       = h0;
                g_Kh[(size_t)(r0 + 8) * 32 + pi] = h1;
                g_Kl[(size_t)r0 * 32 + pi]       = packhf(v00 - f0.x, v01 - f0.y);
                g_Kl[(size_t)(r0 + 8) * 32 + pi] = packhf(v10 - f1.x, v11 - f1.y);
            }
        }
    }
}

// ---------------------------------------------------------------------------
// Kernel 1b: V -> transposed fp16 hi/lo split [tile][dim][keypair].
// ---------------------------------------------------------------------------
__global__ __launch_bounds__(256) void vsplit_kernel()
{
    __shared__ float vs[64][65];
    const int bt  = blockIdx.x;            // 0..255
    const int tid = threadIdx.x;
    const float* base = g_V + (size_t)bt * 64 * 64;

    #pragma unroll
    for (int i = 0; i < 16; i++) {
        int id = i * 256 + tid;
        vs[id >> 6][id & 63] = base[id];
    }
    __syncthreads();

    const int d   = tid >> 2;
    const int kpb = (tid & 3) * 8;
    uint32_t* oh = g_Vth + (size_t)bt * 2048 + d * 32;
    uint32_t* ol = g_Vtl + (size_t)bt * 2048 + d * 32;
    #pragma unroll
    for (int j = 0; j < 8; j++) {
        int kp = kpb + j;
        float v0 = vs[2 * kp][d];
        float v1 = vs[2 * kp + 1][d];
        uint32_t hp = packhf(v0, v1);
        float2 f = unpackhf(hp);
        oh[kp] = hp;
        ol[kp] = packhf(v0 - f.x, v1 - f.y);
    }
}

// ---------------------------------------------------------------------------
// Kernel 2: split-KV causal flash attention, mma.sync fp16 asymmetric split:
//   S = Q_f16 * (K_hi + K_lo),  O = P_f16 * (V_hi + V_lo).
// Split size 8 tiles -> grid (80, 8) LPT-decoded; block 128 = 4 warps.
// Single-buffered static smem (36.9 KB) -> 4-5 CTAs/SM; occupancy covers the
// unpipelined cp.async latency.  Single-split q-blocks (t<8) write output
// directly; others write (o,m,l) partials.
// ---------------------------------------------------------------------------
__global__ __launch_bounds__(128) void attn_split_kernel(float* __restrict__ out)
{
    __shared__ uint32_t sKH[2304], sKL[2304], sVH[2304], sVL[2304];

    const int bxr = 79 - (int)blockIdx.x;   // heavy first (LPT)
    const int b   = blockIdx.y;

    int g = 0;
    if (bxr >= 8)  g = 1;
    if (bxr >= 24) g = 2;
    if (bxr >= 48) g = 3;
    const int rem = bxr - 4 * g * (g + 1);
    const int qi  = rem / (g + 1);
    const int s   = rem - qi * (g + 1);
    const int t   = 8 * g + qi;              // q-block 0..31

    const int tid  = threadIdx.x;
    const int w    = tid >> 5;
    const int lane = tid & 31;
    const int gid  = lane >> 2;
    const int tg   = lane & 3;
    const int r0   = t * 64 + w * 16 + gid;  // q row (in-batch); second row r0+8

    // Q A-fragments (single fp16)
    uint32_t qh[4][4];
    {
        const uint32_t* qhp = g_Qh + ((size_t)b * T_ + r0) * 32;
        #pragma unroll
        for (int kk = 0; kk < 4; kk++) {
            qh[kk][0] = qhp[kk * 8 + tg];
            qh[kk][1] = qhp[8 * 32 + kk * 8 + tg];
            qh[kk][2] = qhp[kk * 8 + tg + 4];
            qh[kk][3] = qhp[8 * 32 + kk * 8 + tg + 4];
        }
    }

    float o[8][4];
    #pragma unroll
    for (int nt = 0; nt < 8; nt++)
        #pragma unroll
        for (int i = 0; i < 4; i++) o[nt][i] = 0.0f;
    float m0v = -1e30f, m1v = -1e30f, l0 = 0.0f, l1 = 0.0f;

    const uint32_t kh_b = smem_u32(sKH), kl_b = smem_u32(sKL);
    const uint32_t vh_b = smem_u32(sVH), vl_b = smem_u32(sVL);

    int lrow[4], lgq[4];
    #pragma unroll
    for (int i = 0; i < 4; i++) {
        int c = i * 128 + tid;
        lrow[i] = c >> 3;
        lgq[i]  = c & 7;
    }

    const int t0 = s * 8;
    const int t1 = min(s * 8 + 8, t + 1);

    for (int tt = t0; tt < t1; tt++) {
        // load all four operand tiles
        {
            const size_t krow = (size_t)b * T_ + tt * 64;
            const size_t vbs  = ((size_t)b * 32 + tt) * 2048;
            #pragma unroll
            for (int i = 0; i < 4; i++) {
                uint32_t doff = (uint32_t)(lrow[i] * 36 + lgq[i] * 4) * 4;
                uint32_t koff = (krow + lrow[i]) * 32 + lgq[i] * 4;
                uint32_t voff = lrow[i] * 32 + lgq[i] * 4;
                cp_async16(kh_b + doff, g_Kh + koff);
                cp_async16(kl_b + doff, g_Kl + koff);
                cp_async16(vh_b + doff, g_Vth + vbs + voff);
                cp_async16(vl_b + doff, g_Vtl + vbs + voff);
            }
            CP_COMMIT();
            CP_WAIT0();
        }
        __syncthreads();

        // ---- S = Q K^T (2-mma) ----
        float st[8][4];
        #pragma unroll
        for (int nt = 0; nt < 8; nt++)
            #pragma unroll
            for (int i = 0; i < 4; i++) st[nt][i] = 0.0f;

        #pragma unroll
        for (int kk = 0; kk < 4; kk++) {
            #pragma unroll
            for (int nt = 0; nt < 8; nt++) {
                const uint32_t base = (uint32_t)(nt * 8 + gid) * 36u + kk * 8 + tg;
                uint32_t bh0 = sKH[base], bh1 = sKH[base + 4];
                uint32_t bl0 = sKL[base], bl1 = sKL[base + 4];
                mma_f16(st[nt], qh[kk][0], qh[kk][1], qh[kk][2], qh[kk][3], bh0, bh1);
                mma_f16(st[nt], qh[kk][0], qh[kk][1], qh[kk][2], qh[kk][3], bl0, bl1);
            }
        }

        // causal mask (diagonal tile only)
        if (tt == t) {
            #pragma unroll
            for (int nt = 0; nt < 8; nt++) {
                int c0 = tt * 64 + nt * 8 + 2 * tg;
                if (c0     > r0)     st[nt][0] = -1e30f;
                if (c0 + 1 > r0)     st[nt][1] = -1e30f;
                if (c0     > r0 + 8) st[nt][2] = -1e30f;
                if (c0 + 1 > r0 + 8) st[nt][3] = -1e30f;
            }
        }

        // ---- online softmax ----
        float mn0 = m0v, mn1 = m1v;
        #pragma unroll
        for (int nt = 0; nt < 8; nt++) {
            mn0 = fmaxf(mn0, fmaxf(st[nt][0], st[nt][1]));
            mn1 = fmaxf(mn1, fmaxf(st[nt][2], st[nt][3]));
        }
        mn0 = fmaxf(mn0, __shfl_xor_sync(0xffffffffu, mn0, 1));
        mn0 = fmaxf(mn0, __shfl_xor_sync(0xffffffffu, mn0, 2));
        mn1 = fmaxf(mn1, __shfl_xor_sync(0xffffffffu, mn1, 1));
        mn1 = fmaxf(mn1, __shfl_xor_sync(0xffffffffu, mn1, 2));
        const float a0 = __expf(m0v - mn0);
        const float a1 = __expf(m1v - mn1);
        m0v = mn0; m1v = mn1;
        float rs0 = 0.0f, rs1 = 0.0f;
        #pragma unroll
        for (int nt = 0; nt < 8; nt++) {
            st[nt][0] = __expf(st[nt][0] - mn0);
            st[nt][1] = __expf(st[nt][1] - mn0);
            st[nt][2] = __expf(st[nt][2] - mn1);
            st[nt][3] = __expf(st[nt][3] - mn1);
            rs0 += st[nt][0] + st[nt][1];
            rs1 += st[nt][2] + st[nt][3];
        }
        l0 = l0 * a0 + rs0;
        l1 = l1 * a1 + rs1;
        #pragma unroll
        for (int nt = 0; nt < 8; nt++) {
            o[nt][0] *= a0; o[nt][1] *= a0;
            o[nt][2] *= a1; o[nt][3] *= a1;
        }

        // ---- O += P V (2-mma, P single fp16) ----
        #pragma unroll
        for (int kk = 0; kk < 4; kk++) {
            uint32_t ph[4];
            ph[0] = packhf(st[2 * kk][0],     st[2 * kk][1]);
            ph[1] = packhf(st[2 * kk][2],     st[2 * kk][3]);
            ph[2] = packhf(st[2 * kk + 1][0], st[2 * kk + 1][1]);
            ph[3] = packhf(st[2 * kk + 1][2], st[2 * kk + 1][3]);
            #pragma unroll
            for (int nd = 0; nd < 8; nd++) {
                const uint32_t base = (uint32_t)(nd * 8 + gid) * 36u + kk * 8 + tg;
                uint32_t vh0 = sVH[base], vh1 = sVH[base + 4];
                uint32_t vl0 = sVL[base], vl1 = sVL[base + 4];
                mma_f16(o[nd], ph[0], ph[1], ph[2], ph[3], vh0, vh1);
                mma_f16(o[nd], ph[0], ph[1], ph[2], ph[3], vl0, vl1);
            }
        }
        __syncthreads();   // smem reuse barrier before next tile's loads
    }

    // full-row l (quartet reduce)
    l0 += __shfl_xor_sync(0xffffffffu, l0, 1);
    l0 += __shfl_xor_sync(0xffffffffu, l0, 2);
    l1 += __shfl_xor_sync(0xffffffffu, l1, 1);
    l1 += __shfl_xor_sync(0xffffffffu, l1, 2);

    const int rr = w * 16 + gid;
    if (g == 0) {
        const float i0 = 1.0f / l0, i1 = 1.0f / l1;
        float* o0 = out + ((size_t)b * T_ + t * 64 + rr) * H_;
        float* o1 = out + ((size_t)b * T_ + t * 64 + rr + 8) * H_;
        #pragma unroll
        for (int nt = 0; nt < 8; nt++) {
            const int col = nt * 8 + 2 * tg;
            *(float2*)(o0 + col) = make_float2(o[nt][0] * i0, o[nt][1] * i0);
            *(float2*)(o1 + col) = make_float2(o[nt][2] * i1, o[nt][3] * i1);
        }
    } else {
        float* op0 = &g_Op[b][t][s][rr][0];
        float* op1 = &g_Op[b][t][s][rr + 8][0];
        #pragma unroll
        for (int nt = 0; nt < 8; nt++) {
            const int col = nt * 8 + 2 * tg;
            *(float2*)(op0 + col) = make_float2(o[nt][0], o[nt][1]);
            *(float2*)(op1 + col) = make_float2(o[nt][2], o[nt][3]);
        }
        if (tg == 0) {
            g_Ml[b][t][s][rr][0]     = m0v;
            g_Ml[b][t][s][rr][1]     = l0;
            g_Ml[b][t][s][rr + 8][0] = m1v;
            g_Ml[b][t][s][rr + 8][1] = l1;
        }
    }
}

// ---------------------------------------------------------------------------
// Kernel 3: combine split partials (only q-blocks t >= 8).
// ---------------------------------------------------------------------------
__global__ __launch_bounds__(256) void attn_combine_kernel(float* __restrict__ out)
{
    const int t   = 8 + blockIdx.x;          // 8..31
    const int b   = blockIdx.y;
    const int tid = threadIdx.x;
    const int r   = tid >> 2;
    const int q4  = tid & 3;
    const int dbase = q4 * 16;
    const int ns  = t / 8 + 1;               // 2..4

    float mv[4], lv[4], wv[4];
    float M = -1e30f;
    for (int i = 0; i < ns; i++) {
        mv[i] = g_Ml[b][t][i][r][0];
        lv[i] = g_Ml[b][t][i][r][1];
        M = fmaxf(M, mv[i]);
    }
    float L = 0.0f;
    for (int i = 0; i < ns; i++) {
        wv[i] = __expf(mv[i] - M);
        L += wv[i] * lv[i];
    }
    const float invL = 1.0f / L;

    float acc[16];
    #pragma unroll
    for (int d = 0; d < 16; d++) acc[d] = 0.0f;

    for (int i = 0; i < ns; i++) {
        const float* op = &g_Op[b][t][i][r][dbase];
        const float wi = wv[i];
        #pragma unroll
        for (int d4 = 0; d4 < 4; d4++) {
            float4 v = *(const float4*)(op + d4 * 4);
            acc[d4 * 4 + 0] += wi * v.x;
            acc[d4 * 4 + 1] += wi * v.y;
            acc[d4 * 4 + 2] += wi * v.z;
            acc[d4 * 4 + 3] += wi * v.w;
        }
    }

    float* orow = out + ((size_t)b * T_ + t * 64 + r) * H_ + dbase;
    #pragma unroll
    for (int d4 = 0; d4 < 4; d4++) {
        float4 v;
        v.x = acc[d4 * 4 + 0] * invL;
        v.y = acc[d4 * 4 + 1] * invL;
        v.z = acc[d4 * 4 + 2] * invL;
        v.w = acc[d4 * 4 + 3] * invL;
        *(float4*)(orow + d4 * 4) = v;
    }
}

// ---------------------------------------------------------------------------
extern "C" void kernel_launch(void* const* d_in, const int* in_sizes, int n_in,
                              void* d_out, int out_size)
{
    const float* x  = (const float*)d_in[0];
    const float* Wq = (const float*)d_in[1];
    const float* bq = (const float*)d_in[2];
    const float* Wk = (const float*)d_in[3];
    const float* bk = (const float*)d_in[4];
    const float* Wv = (const float*)d_in[5];
    const float* bv = (const float*)d_in[6];
    float* out = (float*)d_out;

    cudaFuncSetAttribute(qkv_mma_kernel,
                         cudaFuncAttributeMaxDynamicSharedMemorySize, SMEM_DYN);

    wsplit_kernel<<<384, 256>>>(Wq, Wk, Wv);
    qkv_mma_kernel<<<128, 256, SMEM_DYN>>>(x, bq, bk, bv);
    vsplit_kernel<<<256, 256>>>();
    attn_split_kernel<<<dim3(80, B_), 128>>>(out);
    attn_combine_kernel<<<dim3(24, B_), 256>>>(out);
}

// round 10
// speedup vs baseline: 1.2985x; 1.0714x over previous
#include <cuda_runtime.h>
#include <cuda_fp16.h>
#include <cstdint>

#define B_ 8
#define T_ 2048
#define D_ 1024
#define H_ 64
#define M_ (B_ * T_)        // 16384 rows

// ---------------------------------------------------------------------------
// Device scratch
// ---------------------------------------------------------------------------
__device__ float g_V[M_ * H_];                      // fp32 V (intermediate)
__device__ uint32_t g_Qh[M_ * 32];                  // packed fp16 Q (pre-scaled)
__device__ uint32_t g_Kh[M_ * 32], g_Kl[M_ * 32];   // packed fp16 hi/lo K
__device__ uint32_t g_Vth[256 * 64 * 32];           // V^T fp16 hi, [tile][dim][keypair]
__device__ uint32_t g_Vtl[256 * 64 * 32];           // V^T fp16 lo

// W transposed, fp16 hi/lo split, packed 2-per-u32 along k
__device__ uint32_t g_Whl[6][64][512];

// Split-KV partials: [b][G(128-row block)][split][row][dim]
__device__ float g_Op[B_][16][4][128][H_];
__device__ float g_Ml[B_][16][4][128][2];

// ---------------------------------------------------------------------------
// Helpers
// ---------------------------------------------------------------------------
__device__ __forceinline__ uint32_t smem_u32(const void* p) {
    uint32_t a;
    asm("{ .reg .u64 t; cvta.to.shared.u64 t, %1; cvt.u32.u64 %0, t; }" : "=r"(a) : "l"(p));
    return a;
}
__device__ __forceinline__ uint32_t packhf(float a, float b) {   // a->lo, b->hi
    __half2 h = __floats2half2_rn(a, b);
    return *reinterpret_cast<uint32_t*>(&h);
}
__device__ __forceinline__ float2 unpackhf(uint32_t p) {
    __half2 h = *reinterpret_cast<__half2*>(&p);
    return __half22float2(h);
}
__device__ __forceinline__ void mma_f16(float* c,
    uint32_t a0, uint32_t a1, uint32_t a2, uint32_t a3, uint32_t b0, uint32_t b1)
{
    asm volatile("mma.sync.aligned.m16n8k16.row.col.f32.f16.f16.f32 "
        "{%0,%1,%2,%3}, {%4,%5,%6,%7}, {%8,%9}, {%0,%1,%2,%3};"
        : "+f"(c[0]), "+f"(c[1]), "+f"(c[2]), "+f"(c[3])
        : "r"(a0), "r"(a1), "r"(a2), "r"(a3), "r"(b0), "r"(b1));
}
__device__ __forceinline__ void cp_async16(uint32_t dst, const void* src) {
    asm volatile("cp.async.cg.shared.global [%0], [%1], 16;" :: "r"(dst), "l"(src) : "memory");
}
#define CP_COMMIT()  asm volatile("cp.async.commit_group;" ::: "memory")
#define CP_WAIT1()   asm volatile("cp.async.wait_group 1;"  ::: "memory")
#define CP_WAIT0()   asm volatile("cp.async.wait_group 0;"  ::: "memory")

// ---------------------------------------------------------------------------
// Kernel 0: transpose + fp16 hi/lo split + pack of the three weight matrices.
// ---------------------------------------------------------------------------
__global__ __launch_bounds__(256) void wsplit_kernel(
    const float* __restrict__ Wq, const float* __restrict__ Wk, const float* __restrict__ Wv)
{
    int idx = blockIdx.x * 256 + threadIdx.x;
    int o  = idx >> 15;
    int n  = (idx >> 9) & 63;
    int kp = idx & 511;
    const float* W = (o == 0) ? Wq : (o == 1) ? Wk : Wv;
    float w0 = W[(2 * kp + 0) * 64 + n];
    float w1 = W[(2 * kp + 1) * 64 + n];
    uint32_t hp = packhf(w0, w1);
    float2 f = unpackhf(hp);
    g_Whl[o][n][kp]     = hp;
    g_Whl[3 + o][n][kp] = packhf(w0 - f.x, w1 - f.y);
}

// ---------------------------------------------------------------------------
// Kernel 1: fused QKV projection, mma.sync fp16, asymmetric 2-mma split.
// (unchanged from R9)
// ---------------------------------------------------------------------------
#define STAGE_U   10240
#define SMEM_DYN  (2 * STAGE_U * 4)

__global__ __launch_bounds__(256, 1) void qkv_mma_kernel(
    const float* __restrict__ x,
    const float* __restrict__ bq, const float* __restrict__ bk, const float* __restrict__ bv)
{
    extern __shared__ uint32_t sm[];
    __shared__ float sbias[3][64];

    const int tid  = threadIdx.x;
    const int w    = tid >> 5;
    const int lane = tid & 31;
    const int gid  = lane >> 2;
    const int tg   = lane & 3;
    const int m0   = blockIdx.x * 128;

    if (tid < 64) {
        sbias[0][tid] = bq[tid];
        sbias[1][tid] = bk[tid];
        sbias[2][tid] = bv[tid];
    }

    const int xrow  = tid >> 1;
    const int xhalf = tid & 1;
    const float* xbase = x + (size_t)(m0 + xrow) * D_ + xhalf * 16;

    uint32_t wdst[6];
    const uint32_t* wsrc[6];
    #pragma unroll
    for (int it = 0; it < 6; it++) {
        int sid = it * 256 + tid;
        int j = sid >> 8, n = (sid >> 2) & 63, gq = sid & 3;
        wdst[it] = 2560u + (uint32_t)j * 1280u + (uint32_t)n * 20u + (uint32_t)gq * 4u;
        wsrc[it] = &g_Whl[j][n][gq * 4];
    }
    const uint32_t smbase = smem_u32(sm);

    float acc[3][8][4];
    #pragma unroll
    for (int o = 0; o < 3; o++)
        #pragma unroll
        for (int nt = 0; nt < 8; nt++)
            #pragma unroll
            for (int i = 0; i < 4; i++) acc[o][nt][i] = 0.0f;

    #pragma unroll
    for (int it = 0; it < 6; it++)
        cp_async16(smbase + wdst[it] * 4, wsrc[it]);
    CP_COMMIT();

    float4 xv[2][4];
    #pragma unroll
    for (int i = 0; i < 4; i++) xv[0][i] = *(const float4*)(xbase + i * 4);

    #pragma unroll 2
    for (int s = 0; s < 32; s++) {
        const int p   = s & 1;
        const int np  = p ^ 1;
        const uint32_t st = (uint32_t)p * STAGE_U;

        if (s + 1 < 32) {
            #pragma unroll
            for (int it = 0; it < 6; it++)
                cp_async16(smbase + (np * STAGE_U + wdst[it]) * 4,
                           wsrc[it] + (size_t)(s + 1) * 16);
        }
        CP_COMMIT();
        if (s + 1 < 32) {
            const float* xp = xbase + (s + 1) * 32;
            #pragma unroll
            for (int i = 0; i < 4; i++) xv[np][i] = *(const float4*)(xp + i * 4);
        }

        {
            uint32_t hp[8];
            #pragma unroll
            for (int i = 0; i < 4; i++) {
                float4 v = xv[p][i];
                hp[i * 2 + 0] = packhf(v.x, v.y);
                hp[i * 2 + 1] = packhf(v.z, v.w);
            }
            uint32_t* xs = &sm[st + (uint32_t)xrow * 20u + (uint32_t)xhalf * 8u];
            *(uint4*)(xs + 0) = make_uint4(hp[0], hp[1], hp[2], hp[3]);
            *(uint4*)(xs + 4) = make_uint4(hp[4], hp[5], hp[6], hp[7]);
        }

        CP_WAIT1();
        __syncthreads();

        const uint32_t arow = st + (uint32_t)(w * 16 + gid) * 20u;
        #pragma unroll
        for (int kk = 0; kk < 2; kk++) {
            const uint32_t ka = arow + kk * 8 + tg;
            uint32_t a0 = sm[ka];
            uint32_t a1 = sm[ka + 8 * 20];
            uint32_t a2 = sm[ka + 4];
            uint32_t a3 = sm[ka + 8 * 20 + 4];
            #pragma unroll
            for (int o = 0; o < 3; o++) {
                #pragma unroll
                for (int nt = 0; nt < 8; nt++) {
                    const uint32_t kb = st + 2560u + (uint32_t)o * 1280u
                                      + (uint32_t)(nt * 8 + gid) * 20u + kk * 8 + tg;
                    uint32_t bh0 = sm[kb];
                    uint32_t bh1 = sm[kb + 4];
                    uint32_t bl0 = sm[kb + 3 * 1280];
                    uint32_t bl1 = sm[kb + 3 * 1280 + 4];
                    mma_f16(acc[o][nt], a0, a1, a2, a3, bh0, bh1);
                    mma_f16(acc[o][nt], a0, a1, a2, a3, bl0, bl1);
                }
            }
        }
        __syncthreads();
    }

    const int r0 = m0 + w * 16 + gid;
    #pragma unroll
    for (int o = 0; o < 3; o++) {
        const float scale = (o == 0) ? 0.125f : 1.0f;
        #pragma unroll
        for (int nt = 0; nt < 8; nt++) {
            const int col = nt * 8 + 2 * tg;
            float v00 = (acc[o][nt][0] + sbias[o][col])     * scale;
            float v01 = (acc[o][nt][1] + sbias[o][col + 1]) * scale;
            float v10 = (acc[o][nt][2] + sbias[o][col])     * scale;
            float v11 = (acc[o][nt][3] + sbias[o][col + 1]) * scale;
            const int pi = nt * 4 + tg;
            if (o == 2) {
                *(float2*)(g_V + (size_t)r0 * H_ + col)       = make_float2(v00, v01);
                *(float2*)(g_V + (size_t)(r0 + 8) * H_ + col) = make_float2(v10, v11);
            } else if (o == 0) {
                g_Qh[(size_t)r0 * 32 + pi]       = packhf(v00, v01);
                g_Qh[(size_t)(r0 + 8) * 32 + pi] = packhf(v10, v11);
            } else {
                uint32_t h0 = packhf(v00, v01);
                uint32_t h1 = packhf(v10, v11);
                float2 f0 = unpackhf(h0), f1 = unpackhf(h1);
                g_Kh[(size_t)r0 * 32 + pi]       = h0;
                g_Kh[(size_t)(r0 + 8) * 32 + pi] = h1;
                g_Kl[(size_t)r0 * 32 + pi]       = packhf(v00 - f0.x, v01 - f0.y);
                g_Kl[(size_t)(r0 + 8) * 32 + pi] = packhf(v10 - f1.x, v11 - f1.y);
            }
        }
    }
}

// ---------------------------------------------------------------------------
// Kernel 1b: V -> transposed fp16 hi/lo split [tile][dim][keypair].
// ---------------------------------------------------------------------------
__global__ __launch_bounds__(256) void vsplit_kernel()
{
    __shared__ float vs[64][65];
    const int bt  = blockIdx.x;
    const int tid = threadIdx.x;
    const float* base = g_V + (size_t)bt * 64 * 64;

    #pragma unroll
    for (int i = 0; i < 16; i++) {
        int id = i * 256 + tid;
        vs[id >> 6][id & 63] = base[id];
    }
    __syncthreads();

    const int d   = tid >> 2;
    const int kpb = (tid & 3) * 8;
    uint32_t* oh = g_Vth + (size_t)bt * 2048 + d * 32;
    uint32_t* ol = g_Vtl + (size_t)bt * 2048 + d * 32;
    #pragma unroll
    for (int j = 0; j < 8; j++) {
        int kp = kpb + j;
        float v0 = vs[2 * kp][d];
        float v1 = vs[2 * kp + 1][d];
        uint32_t hp = packhf(v0, v1);
        float2 f = unpackhf(hp);
        oh[kp] = hp;
        ol[kp] = packhf(v0 - f.x, v1 - f.y);
    }
}

// ---------------------------------------------------------------------------
// Kernel 2: split-KV causal flash attention, mma.sync fp16 asymmetric split.
// CTA = 128 q-rows (8 warps, 256 thr), 2 CTAs/SM (regs capped 128, 73.7 KB
// dynamic smem).  KV tile = 64 keys, double-buffered cp.async ring.
// Split = 8 kv-tiles; grid (40, 8) LPT-decoded over (G, split).
// G<4 (single split) writes normalized output directly.
// Stage layout (u32, stride 9216): KH @0, KL @2304, VH @4608, VL @6912.
// ---------------------------------------------------------------------------
#define ASTG 9216
#define ATT_SMEM (2 * ASTG * 4)

__global__ __launch_bounds__(256, 2) void attn_split_kernel(float* __restrict__ out)
{
    extern __shared__ uint32_t sa[];

    const int bxr = 39 - (int)blockIdx.x;   // heavy first (LPT)
    const int b   = blockIdx.y;

    int h = 0;
    if (bxr >= 4)  h = 1;
    if (bxr >= 12) h = 2;
    if (bxr >= 24) h = 3;
    const int rem = bxr - 2 * h * (h + 1);
    const int qi  = rem / (h + 1);
    const int s   = rem - qi * (h + 1);
    const int G   = 4 * h + qi;              // 128-row q-block 0..15

    const int tid  = threadIdx.x;
    const int w    = tid >> 5;               // 0..7
    const int lane = tid & 31;
    const int gid  = lane >> 2;
    const int tg   = lane & 3;
    const int r0   = G * 128 + w * 16 + gid; // q row (in-batch); second row r0+8

    // Q A-fragments (single fp16)
    uint32_t qh[4][4];
    {
        const uint32_t* qhp = g_Qh + ((size_t)b * T_ + r0) * 32;
        #pragma unroll
        for (int kk = 0; kk < 4; kk++) {
            qh[kk][0] = qhp[kk * 8 + tg];
            qh[kk][1] = qhp[8 * 32 + kk * 8 + tg];
            qh[kk][2] = qhp[kk * 8 + tg + 4];
            qh[kk][3] = qhp[8 * 32 + kk * 8 + tg + 4];
        }
    }

    float o[8][4];
    #pragma unroll
    for (int nt = 0; nt < 8; nt++)
        #pragma unroll
        for (int i = 0; i < 4; i++) o[nt][i] = 0.0f;
    float m0v = -1e30f, m1v = -1e30f, l0 = 0.0f, l1 = 0.0f;

    const uint32_t sab = smem_u32(sa);
    // per-thread tile-load addressing: 2 chunks per array (256 thr x 16B x 2)
    int lrow[2], lgq[2];
    #pragma unroll
    for (int i = 0; i < 2; i++) {
        int c = i * 256 + tid;
        lrow[i] = c >> 3;
        lgq[i]  = c & 7;
    }

    const int t0 = s * 8;
    const int t1 = min(s * 8 + 8, 2 * G + 2);
    const int ntile = t1 - t0;

    // prologue: tile t0 -> stage 0
    {
        const size_t krow = (size_t)b * T_ + t0 * 64;
        const size_t vbs  = ((size_t)b * 32 + t0) * 2048;
        #pragma unroll
        for (int i = 0; i < 2; i++) {
            uint32_t doff = (uint32_t)(lrow[i] * 36 + lgq[i] * 4) * 4;
            uint32_t koff = (krow + lrow[i]) * 32 + lgq[i] * 4;
            uint32_t voff = lrow[i] * 32 + lgq[i] * 4;
            cp_async16(sab + doff,             g_Kh + koff);
            cp_async16(sab + 2304 * 4 + doff,  g_Kl + koff);
            cp_async16(sab + 4608 * 4 + doff,  g_Vth + vbs + voff);
            cp_async16(sab + 6912 * 4 + doff,  g_Vtl + vbs + voff);
        }
        CP_COMMIT();
    }

    for (int ti = 0; ti < ntile; ti++) {
        const int tt = t0 + ti;
        const int p  = ti & 1;
        const uint32_t stp = (uint32_t)p * ASTG;

        if (ti + 1 < ntile) {
            const uint32_t stn = (uint32_t)(p ^ 1) * ASTG * 4;
            const size_t krow = (size_t)b * T_ + (tt + 1) * 64;
            const size_t vbs  = ((size_t)b * 32 + (tt + 1)) * 2048;
            #pragma unroll
            for (int i = 0; i < 2; i++) {
                uint32_t doff = stn + (uint32_t)(lrow[i] * 36 + lgq[i] * 4) * 4;
                uint32_t koff = (krow + lrow[i]) * 32 + lgq[i] * 4;
                uint32_t voff = lrow[i] * 32 + lgq[i] * 4;
                cp_async16(sab + doff,             g_Kh + koff);
                cp_async16(sab + 2304 * 4 + doff,  g_Kl + koff);
                cp_async16(sab + 4608 * 4 + doff,  g_Vth + vbs + voff);
                cp_async16(sab + 6912 * 4 + doff,  g_Vtl + vbs + voff);
            }
            CP_COMMIT();
            CP_WAIT1();
        } else {
            CP_WAIT0();
        }
        __syncthreads();

        // ---- S = Q K^T (2-mma) ----
        float st[8][4];
        #pragma unroll
        for (int nt = 0; nt < 8; nt++)
            #pragma unroll
            for (int i = 0; i < 4; i++) st[nt][i] = 0.0f;

        #pragma unroll
        for (int kk = 0; kk < 4; kk++) {
            #pragma unroll
            for (int nt = 0; nt < 8; nt++) {
                const uint32_t base = stp + (uint32_t)(nt * 8 + gid) * 36u + kk * 8 + tg;
                uint32_t bh0 = sa[base],        bh1 = sa[base + 4];
                uint32_t bl0 = sa[base + 2304], bl1 = sa[base + 2304 + 4];
                mma_f16(st[nt], qh[kk][0], qh[kk][1], qh[kk][2], qh[kk][3], bh0, bh1);
                mma_f16(st[nt], qh[kk][0], qh[kk][1], qh[kk][2], qh[kk][3], bl0, bl1);
            }
        }

        // causal mask: only the two diagonal tiles of this 128-row block
        if (tt >= 2 * G) {
            #pragma unroll
            for (int nt = 0; nt < 8; nt++) {
                int c0 = tt * 64 + nt * 8 + 2 * tg;
                if (c0     > r0)     st[nt][0] = -1e30f;
                if (c0 + 1 > r0)     st[nt][1] = -1e30f;
                if (c0     > r0 + 8) st[nt][2] = -1e30f;
                if (c0 + 1 > r0 + 8) st[nt][3] = -1e30f;
            }
        }

        // ---- online softmax ----
        float mn0 = m0v, mn1 = m1v;
        #pragma unroll
        for (int nt = 0; nt < 8; nt++) {
            mn0 = fmaxf(mn0, fmaxf(st[nt][0], st[nt][1]));
            mn1 = fmaxf(mn1, fmaxf(st[nt][2], st[nt][3]));
        }
        mn0 = fmaxf(mn0, __shfl_xor_sync(0xffffffffu, mn0, 1));
        mn0 = fmaxf(mn0, __shfl_xor_sync(0xffffffffu, mn0, 2));
        mn1 = fmaxf(mn1, __shfl_xor_sync(0xffffffffu, mn1, 1));
        mn1 = fmaxf(mn1, __shfl_xor_sync(0xffffffffu, mn1, 2));
        const float a0 = __expf(m0v - mn0);
        const float a1 = __expf(m1v - mn1);
        m0v = mn0; m1v = mn1;
        float rs0 = 0.0f, rs1 = 0.0f;
        #pragma unroll
        for (int nt = 0; nt < 8; nt++) {
            st[nt][0] = __expf(st[nt][0] - mn0);
            st[nt][1] = __expf(st[nt][1] - mn0);
            st[nt][2] = __expf(st[nt][2] - mn1);
            st[nt][3] = __expf(st[nt][3] - mn1);
            rs0 += st[nt][0] + st[nt][1];
            rs1 += st[nt][2] + st[nt][3];
        }
        l0 = l0 * a0 + rs0;
        l1 = l1 * a1 + rs1;
        #pragma unroll
        for (int nt = 0; nt < 8; nt++) {
            o[nt][0] *= a0; o[nt][1] *= a0;
            o[nt][2] *= a1; o[nt][3] *= a1;
        }

        // ---- O += P V (2-mma, P single fp16) ----
        #pragma unroll
        for (int kk = 0; kk < 4; kk++) {
            uint32_t ph[4];
            ph[0] = packhf(st[2 * kk][0],     st[2 * kk][1]);
            ph[1] = packhf(st[2 * kk][2],     st[2 * kk][3]);
            ph[2] = packhf(st[2 * kk + 1][0], st[2 * kk + 1][1]);
            ph[3] = packhf(st[2 * kk + 1][2], st[2 * kk + 1][3]);
            #pragma unroll
            for (int nd = 0; nd < 8; nd++) {
                const uint32_t base = stp + 4608u + (uint32_t)(nd * 8 + gid) * 36u + kk * 8 + tg;
                uint32_t vh0 = sa[base],        vh1 = sa[base + 4];
                uint32_t vl0 = sa[base + 2304], vl1 = sa[base + 2304 + 4];
                mma_f16(o[nd], ph[0], ph[1], ph[2], ph[3], vh0, vh1);
                mma_f16(o[nd], ph[0], ph[1], ph[2], ph[3], vl0, vl1);
            }
        }
        __syncthreads();   // all warps done with stage p before it is refilled
    }

    // full-row l (quartet reduce)
    l0 += __shfl_xor_sync(0xffffffffu, l0, 1);
    l0 += __shfl_xor_sync(0xffffffffu, l0, 2);
    l1 += __shfl_xor_sync(0xffffffffu, l1, 1);
    l1 += __shfl_xor_sync(0xffffffffu, l1, 2);

    const int rr = w * 16 + gid;
    if (h == 0) {
        const float i0 = 1.0f / l0, i1 = 1.0f / l1;
        float* o0 = out + ((size_t)b * T_ + G * 128 + rr) * H_;
        float* o1 = out + ((size_t)b * T_ + G * 128 + rr + 8) * H_;
        #pragma unroll
        for (int nt = 0; nt < 8; nt++) {
            const int col = nt * 8 + 2 * tg;
            *(float2*)(o0 + col) = make_float2(o[nt][0] * i0, o[nt][1] * i0);
            *(float2*)(o1 + col) = make_float2(o[nt][2] * i1, o[nt][3] * i1);
        }
    } else {
        float* op0 = &g_Op[b][G][s][rr][0];
        float* op1 = &g_Op[b][G][s][rr + 8][0];
        #pragma unroll
        for (int nt = 0; nt < 8; nt++) {
            const int col = nt * 8 + 2 * tg;
            *(float2*)(op0 + col) = make_float2(o[nt][0], o[nt][1]);
            *(float2*)(op1 + col) = make_float2(o[nt][2], o[nt][3]);
        }
        if (tg == 0) {
            g_Ml[b][G][s][rr][0]     = m0v;
            g_Ml[b][G][s][rr][1]     = l0;
            g_Ml[b][G][s][rr + 8][0] = m1v;
            g_Ml[b][G][s][rr + 8][1] = l1;
        }
    }
}

// ---------------------------------------------------------------------------
// Kernel 3: combine split partials (G >= 4).  grid (24, 8): G = 4 + bx/2,
// half = bx&1 selects rows [half*64, half*64+64).
// ---------------------------------------------------------------------------
__global__ __launch_bounds__(256) void attn_combine_kernel(float* __restrict__ out)
{
    const int G    = 4 + (blockIdx.x >> 1);
    const int half = blockIdx.x & 1;
    const int b    = blockIdx.y;
    const int tid  = threadIdx.x;
    const int r    = half * 64 + (tid >> 2);  // 0..127
    const int q4   = tid & 3;
    const int dbase = q4 * 16;
    const int ns   = G / 4 + 1;               // 2..4

    float mv[4], lv[4], wv[4];
    float M = -1e30f;
    for (int i = 0; i < ns; i++) {
        mv[i] = g_Ml[b][G][i][r][0];
        lv[i] = g_Ml[b][G][i][r][1];
        M = fmaxf(M, mv[i]);
    }
    float L = 0.0f;
    for (int i = 0; i < ns; i++) {
        wv[i] = __expf(mv[i] - M);
        L += wv[i] * lv[i];
    }
    const float invL = 1.0f / L;

    float acc[16];
    #pragma unroll
    for (int d = 0; d < 16; d++) acc[d] = 0.0f;

    for (int i = 0; i < ns; i++) {
        const float* op = &g_Op[b][G][i][r][dbase];
        const float wi = wv[i];
        #pragma unroll
        for (int d4 = 0; d4 < 4; d4++) {
            float4 v = *(const float4*)(op + d4 * 4);
            acc[d4 * 4 + 0] += wi * v.x;
            acc[d4 * 4 + 1] += wi * v.y;
            acc[d4 * 4 + 2] += wi * v.z;
            acc[d4 * 4 + 3] += wi * v.w;
        }
    }

    float* orow = out + ((size_t)b * T_ + G * 128 + r) * H_ + dbase;
    #pragma unroll
    for (int d4 = 0; d4 < 4; d4++) {
        float4 v;
        v.x = acc[d4 * 4 + 0] * invL;
        v.y = acc[d4 * 4 + 1] * invL;
        v.z = acc[d4 * 4 + 2] * invL;
        v.w = acc[d4 * 4 + 3] * invL;
        *(float4*)(orow + d4 * 4) = v;
    }
}

// ---------------------------------------------------------------------------
extern "C" void kernel_launch(void* const* d_in, const int* in_sizes, int n_in,
                              void* d_out, int out_size)
{
    const float* x  = (const float*)d_in[0];
    const float* Wq = (const float*)d_in[1];
    const float* bq = (const float*)d_in[2];
    const float* Wk = (const float*)d_in[3];
    const float* bk = (const float*)d_in[4];
    const float* Wv = (const float*)d_in[5];
    const float* bv = (const float*)d_in[6];
    float* out = (float*)d_out;

    cudaFuncSetAttribute(qkv_mma_kernel,
                         cudaFuncAttributeMaxDynamicSharedMemorySize, SMEM_DYN);
    cudaFuncSetAttribute(attn_split_kernel,
                         cudaFuncAttributeMaxDynamicSharedMemorySize, ATT_SMEM);

    wsplit_kernel<<<384, 256>>>(Wq, Wk, Wv);
    qkv_mma_kernel<<<128, 256, SMEM_DYN>>>(x, bq, bk, bv);
    vsplit_kernel<<<256, 256>>>();
    attn_split_kernel<<<dim3(40, B_), 256, ATT_SMEM>>>(out);
    attn_combine_kernel<<<dim3(24, B_), 256>>>(out);
}